// round 11
// baseline (speedup 1.0000x reference)
#include <cuda_runtime.h>

// Problem constants
#define NB    32
#define NH    64
#define NW    64
#define NT    100
#define COUT  8
#define KS    6
#define LP    2

// Tiling: 16x16 output tile, each thread computes 2 adjacent output COLUMNS? no:
// thread = (tx, tyy, cz); computes output rows h0+2*tyy+{0,1}, col w0+tx, couts cz*4..+4
#define TILE_W 16
#define TILE_H 16
#define HALO_W (TILE_W + KS - 1)   // 21
#define HALO_H (TILE_H + KS - 1)   // 21
#define NPIX   (HALO_W * HALO_W)   // 441
#define NTHR   256                 // 16 x 8 x 2
#define CPT    4                   // couts per thread
#define RY     2                   // output rows per thread
#define NCH    13                  // chunks 0..11: 8 timesteps, chunk 12: 4
#define NHWT   (NH * NW * NT)
#define PSTRIDE 6                  // u64 per pixel (48B): 16B-aligned, conflict-free
#define ROWU   (HALO_W * PSTRIDE)  // 126 u64 per smem row
#define NBUF   3

typedef unsigned long long u64;

__device__ __forceinline__ void upk2(u64 v, float& lo, float& hi) {
    asm("mov.b64 {%0, %1}, %2;" : "=f"(lo), "=f"(hi) : "l"(v));
}
__device__ __forceinline__ u64 fma2(u64 a, u64 b, u64 c) {
    u64 d; asm("fma.rn.f32x2 %0, %1, %2, %3;" : "=l"(d) : "l"(a), "l"(b), "l"(c)); return d;
}
__device__ __forceinline__ unsigned smem_u32(const void* p) {
    return (unsigned)__cvta_generic_to_shared(p);
}
__device__ __forceinline__ void cp16(unsigned dst, const void* src) {
    asm volatile("cp.async.ca.shared.global [%0], [%1], 16;" :: "r"(dst), "l"(src));
}
__device__ __forceinline__ void cp_commit() { asm volatile("cp.async.commit_group;" ::: "memory"); }
__device__ __forceinline__ void cp_wait1()  { asm volatile("cp.async.wait_group 1;" ::: "memory"); }
__device__ __forceinline__ void cp_wait0()  { asm volatile("cp.async.wait_group 0;" ::: "memory"); }

// exact reference recurrence step
__device__ __forceinline__ float stepf(float& u, float wx, float thr) {
    u = (u - (u > 0.f ? thr : 0.f)) + wx;
    return (u > 0.f) ? 1.f : 0.f;
}

__global__ __launch_bounds__(NTHR, 2)
void sconv_spike_kernel(const float* __restrict__ x,
                        const float* __restrict__ w,
                        const float* __restrict__ thr_p,
                        float* __restrict__ out)
{
    // triple-buffered halo tile: 21 rows x 21 pixels x 48B
    __shared__ __align__(16) u64 sx[NBUF][HALO_H * ROWU];
    // weights tap-major: sw2[tap*8 + cout], duplicated (w,w) for f32x2
    __shared__ __align__(16) u64 sw2[KS * KS * COUT];

    const int tx  = threadIdx.x;
    const int tyy = threadIdx.y;          // 0..7 -> output rows 2*tyy, 2*tyy+1
    const int cz  = threadIdx.z;
    const int tid = tx + TILE_W * tyy + (TILE_W * 8) * cz;
    const int b   = blockIdx.z;
    const int h0  = blockIdx.y * TILE_H;
    const int w0  = blockIdx.x * TILE_W;

    for (int i = tid; i < KS * KS * COUT; i += NTHR) {
        int tap = i >> 3, c = i & 7;
        unsigned bits = __float_as_uint(w[c * (KS * KS) + tap]);
        sw2[i] = ((u64)bits << 32) | (u64)bits;
    }
    // zero OOB halo pixels once
    for (int pix = tid; pix < NPIX; pix += NTHR) {
        int r = pix / HALO_W, c = pix % HALO_W;
        int gh = h0 - LP + r, gw = w0 - LP + c;
        if (gh < 0 || gh >= NH || gw < 0 || gw >= NW) {
#pragma unroll
            for (int bb = 0; bb < NBUF; bb++)
#pragma unroll
                for (int j = 0; j < 4; j++)
                    sx[bb][r * ROWU + c * PSTRIDE + j] = 0ull;
        }
    }
    const float thr = thr_p[0];

    const float* xb = x + (size_t)b * NH * NW * NT;
    const int cbase = cz * CPT;
    // output bases for the 2 rows this thread owns
    float* ob0 = out + (size_t)b * COUT * NHWT
                     + ((size_t)(h0 + 2 * tyy) * NW + (w0 + tx)) * NT
                     + (size_t)cbase * NHWT;
    float* ob1 = ob0 + (size_t)NW * NT;   // next row

    float ut[RY][CPT];
#pragma unroll
    for (int rr = 0; rr < RY; rr++)
#pragma unroll
        for (int c = 0; c < CPT; c++) ut[rr][c] = 0.f;

    auto load_chunk = [&](int k) {
        int buf = k % NBUF;
        int t0  = k * 8;
        int n16 = (k == NCH - 1) ? 1 : 2;
        int total = NPIX * n16;
        for (int idx = tid; idx < total; idx += NTHR) {
            int pix, j;
            if (n16 == 2) { pix = idx >> 1; j = idx & 1; }
            else          { pix = idx;      j = 0; }
            int r = pix / HALO_W, c = pix % HALO_W;
            int gh = h0 - LP + r, gw = w0 - LP + c;
            if (gh >= 0 && gh < NH && gw >= 0 && gw < NW) {
                const float* src = xb + ((size_t)gh * NW + gw) * NT + t0 + j * 4;
                cp16(smem_u32(&sx[buf][r * ROWU + c * PSTRIDE + j * 2]), src);
            }
        }
        cp_commit();
    };

    load_chunk(0);
    load_chunk(1);

#pragma unroll 1
    for (int i = 0; i < NCH; i++) {
        if (i + 1 < NCH) cp_wait1();
        else             cp_wait0();
        __syncthreads();
        if (i + 2 < NCH) load_chunk(i + 2);

        const int buf = i % NBUF;
        const int t0  = i * 8;
        const bool full = (i != NCH - 1);
        const u64* sb = &sx[buf][(2 * tyy) * ROWU + tx * PSTRIDE];

        // acc[rr][c] split into 4 u64 (8 timesteps); tail uses first 2
        u64 A0[RY][CPT], A1[RY][CPT], A2[RY][CPT], A3[RY][CPT];
#pragma unroll
        for (int rr = 0; rr < RY; rr++)
#pragma unroll
            for (int c = 0; c < CPT; c++) { A0[rr][c] = 0; A1[rr][c] = 0; A2[rr][c] = 0; A3[rr][c] = 0; }

        if (full) {
            // kh outer (preserves per-accumulator (kh,kw) fma order of prior rounds),
            // rolling x window over rows: row m = 2*tyy + kh (+1) serves both rr.
            // For each kh we load the two rows' pixels per kw; the rr=1 row at kh
            // equals the rr=0 row at kh+1 -> carry it in registers.
            // Register window: cur[kw-independent]: we roll over kh per kw instead:
#pragma unroll
            for (int kw = 0; kw < KS; kw++) {
                // NOTE: accumulation order per accumulator remains kh-major per kw
                // column... to keep the EXACT (kh,kw) order of previous rounds we
                // instead accumulate per-kw into separate partials and add at the
                // end in kw order -- but fp32 addition of partials reorders sums.
                // Previous rounds' order: for kh { for kw { acc += } }.
                // We preserve it: kh outer, kw inner, rolling over kw is useless;
                // so roll over kh: see below.
                (void)kw; break;
            }
            // kh-outer with row carry: x row (2tyy+kh+1) loaded at kh serves rr=1,
            // and the same physical row serves rr=0 at kh+1 -> carry 6 kw-pixels?
            // Too many regs; instead carry per-kw inside the kw loop nested in kh
            // would reload. Compromise: hold the NEXT row's 6 pixels? 6*4 u64 = 48
            // regs -- too many. Final choice: per (kh): load row r0+kh pixels on
            // the fly per kw (used by rr=0), and row r0+kh+1 per kw (used by rr=1).
            // Rolling: rowB of iteration kh == rowA of iteration kh+1: carry ONE
            // pixel per kw step is not possible across kh. Accept 2 loads per
            // (kh,kw) but NOTE both rr share one weight load (halves w-LDS) and
            // outputs per thread doubled -> wavefronts/output still ~1.6x better.
#pragma unroll
            for (int kh = 0; kh < KS; kh++) {
#pragma unroll
                for (int kw = 0; kw < KS; kw++) {
                    const int tap = kh * KS + kw;
                    const u64* pA = sb + kh * ROWU + kw * PSTRIDE;        // row for rr=0
                    const u64* pB = pA + ROWU;                             // row for rr=1
                    ulonglong2 a01 = *(const ulonglong2*)(pA);
                    ulonglong2 a23 = *(const ulonglong2*)(pA + 2);
                    ulonglong2 b01 = *(const ulonglong2*)(pB);
                    ulonglong2 b23 = *(const ulonglong2*)(pB + 2);
                    ulonglong2 wA = *(const ulonglong2*)&sw2[tap * COUT + cbase];
                    ulonglong2 wB = *(const ulonglong2*)&sw2[tap * COUT + cbase + 2];
#pragma unroll
                    for (int c = 0; c < CPT; c++) {
                        u64 wc = (c == 0) ? wA.x : (c == 1) ? wA.y : (c == 2) ? wB.x : wB.y;
                        A0[0][c] = fma2(a01.x, wc, A0[0][c]);
                        A1[0][c] = fma2(a01.y, wc, A1[0][c]);
                        A2[0][c] = fma2(a23.x, wc, A2[0][c]);
                        A3[0][c] = fma2(a23.y, wc, A3[0][c]);
                        A0[1][c] = fma2(b01.x, wc, A0[1][c]);
                        A1[1][c] = fma2(b01.y, wc, A1[1][c]);
                        A2[1][c] = fma2(b23.x, wc, A2[1][c]);
                        A3[1][c] = fma2(b23.y, wc, A3[1][c]);
                    }
                }
            }
#pragma unroll
            for (int rr = 0; rr < RY; rr++) {
                float* ob = (rr == 0) ? ob0 : ob1;
#pragma unroll
                for (int c = 0; c < CPT; c++) {
                    float wx0, wx1, wx2, wx3, wx4, wx5, wx6, wx7;
                    upk2(A0[rr][c], wx0, wx1); upk2(A1[rr][c], wx2, wx3);
                    upk2(A2[rr][c], wx4, wx5); upk2(A3[rr][c], wx6, wx7);
                    float u = ut[rr][c];
                    float s0 = stepf(u, wx0, thr), s1 = stepf(u, wx1, thr);
                    float s2 = stepf(u, wx2, thr), s3 = stepf(u, wx3, thr);
                    float s4 = stepf(u, wx4, thr), s5 = stepf(u, wx5, thr);
                    float s6 = stepf(u, wx6, thr), s7 = stepf(u, wx7, thr);
                    ut[rr][c] = u;
                    float4* p = (float4*)(ob + (size_t)c * NHWT + t0);
                    p[0] = make_float4(s0, s1, s2, s3);
                    p[1] = make_float4(s4, s5, s6, s7);
                }
            }
        } else {
            // tail: t = 96..99
#pragma unroll
            for (int kh = 0; kh < KS; kh++) {
#pragma unroll
                for (int kw = 0; kw < KS; kw++) {
                    const int tap = kh * KS + kw;
                    const u64* pA = sb + kh * ROWU + kw * PSTRIDE;
                    const u64* pB = pA + ROWU;
                    ulonglong2 a01 = *(const ulonglong2*)(pA);
                    ulonglong2 b01 = *(const ulonglong2*)(pB);
                    ulonglong2 wA = *(const ulonglong2*)&sw2[tap * COUT + cbase];
                    ulonglong2 wB = *(const ulonglong2*)&sw2[tap * COUT + cbase + 2];
#pragma unroll
                    for (int c = 0; c < CPT; c++) {
                        u64 wc = (c == 0) ? wA.x : (c == 1) ? wA.y : (c == 2) ? wB.x : wB.y;
                        A0[0][c] = fma2(a01.x, wc, A0[0][c]);
                        A1[0][c] = fma2(a01.y, wc, A1[0][c]);
                        A0[1][c] = fma2(b01.x, wc, A0[1][c]);
                        A1[1][c] = fma2(b01.y, wc, A1[1][c]);
                    }
                }
            }
#pragma unroll
            for (int rr = 0; rr < RY; rr++) {
                float* ob = (rr == 0) ? ob0 : ob1;
#pragma unroll
                for (int c = 0; c < CPT; c++) {
                    float wx0, wx1, wx2, wx3;
                    upk2(A0[rr][c], wx0, wx1); upk2(A1[rr][c], wx2, wx3);
                    float u = ut[rr][c];
                    float s0 = stepf(u, wx0, thr), s1 = stepf(u, wx1, thr);
                    float s2 = stepf(u, wx2, thr), s3 = stepf(u, wx3, thr);
                    ut[rr][c] = u;
                    *(float4*)(ob + (size_t)c * NHWT + t0) = make_float4(s0, s1, s2, s3);
                }
            }
        }
    }
}

extern "C" void kernel_launch(void* const* d_in, const int* in_sizes, int n_in,
                              void* d_out, int out_size)
{
    const float* x   = (const float*)d_in[0];  // [32,1,64,64,100]
    const float* w   = (const float*)d_in[1];  // [8,1,6,6]
    const float* thr = (const float*)d_in[2];  // [1]
    float* out = (float*)d_out;                // [32,8,64,64,100]

    dim3 block(TILE_W, 8, 2);                  // 256 threads; 2 rows x 4 couts each
    dim3 grid(NW / TILE_W, NH / TILE_H, NB);   // (4, 4, 32) = 512 blocks
    sconv_spike_kernel<<<grid, block>>>(x, w, thr, out);
}